// round 16
// baseline (speedup 1.0000x reference)
#include <cuda_runtime.h>
#include <cuda_bf16.h>
#include <math_constants.h>

#define NM 1024
#define HH 256
#define WW 256
#define HW (HH * WW)
#define NQ 16            // stats partial chunks per mask
#define NBLK 24576       // 16384 stats blocks + 8192 zero blocks

// Scratch (no cudaMalloc allowed). Fully overwritten every call.
__device__ unsigned g_pp[NQ * NM];   // packed bbox: (rmin,255-rmax,cmin,255-cmax); 0xFFFFFFFF = empty
__device__ unsigned g_pk[NQ * NM];   // packed counts: hi<<16 | lo
__device__ float    g_gated[NM];
__device__ int      g_klist[NM];
__device__ int      g_kcnt;
__device__ unsigned g_arrive = 0;    // reset by the NMS block at end of each launch

// NMS global scratch (used by ONE block; L2-resident, ~30 KB)
__device__ float4   gx_bx[NM];
__device__ float    gx_csc[NM];
__device__ int      gx_cid[NM];
__device__ float    gx_sc[NM];
__device__ int      gx_ord[NM];
__device__ float    gx_area[NM];
__device__ unsigned gx_sup[256 * 8];

// ---------------------------------------------------------------------------
// Kernel A (fused + last-block NMS): linear grid of 24576 blocks, 256 thr.
//   lin % 3 == 2 -> zero-writer (32 KB of output)      [8192 blocks, 256 MB W]
//   lin % 3 <  2 -> stats partial (16 KB of logits)    [16384 blocks, 256 MB R]
// Period-3 mixing keeps every wave at a steady 1:1 byte-rate read/write mix
// (~80% DRAM). The LAST block to arrive (release/acquire via g_arrive) runs
// the full NMS using global scratch — hot blocks keep 29 regs / 64 B smem.
// ---------------------------------------------------------------------------
__global__ void __launch_bounds__(256) stats_zero_nms_kernel(
        const float* __restrict__ logits,
        float* __restrict__ out,
        const float* __restrict__ iou,
        float* __restrict__ out_keep,
        float* __restrict__ out_boxes,
        int write_extra) {
    __shared__ unsigned s_p[8], s_pk[8];
    __shared__ int s_last, s_cnt, s_kc;
    __shared__ unsigned s_live[8];

    const int lin = blockIdx.x;
    const int tid = threadIdx.x;
    const int rol = lin % 3;
    const int grp = lin / 3;

    if (rol == 2) {
        // ---- zero-writer role: 32 KB = 8 float4/thread ----
        const int n    = grp & (NM - 1);
        const int half = grp >> 10;           // 0..7
        float4* __restrict__ o4 =
            reinterpret_cast<float4*>(out + (size_t)n * HW + (size_t)half * 8192);
        const float4 z = make_float4(0.f, 0.f, 0.f, 0.f);
#pragma unroll
        for (int k = 0; k < 8; k++) o4[k * 256 + tid] = z;
    } else {
        // ---- stats role: 16 rows of one mask ----
        const int sidx = grp * 2 + rol;       // 0..16383
        const int n    = sidx & (NM - 1);
        const int q    = sidx >> 10;          // 0..15
        const int tx   = tid & 63;
        const int ty   = tid >> 6;
        const int col0 = tx * 4;
        const int r0   = q * 16 + ty * 4;

        const float4* __restrict__ base =
            reinterpret_cast<const float4*>(logits + (size_t)n * HW) + tx;

        float4 v0 = base[(size_t)(r0 + 0) * (WW / 4)];
        float4 v1 = base[(size_t)(r0 + 1) * (WW / 4)];
        float4 v2 = base[(size_t)(r0 + 2) * (WW / 4)];
        float4 v3 = base[(size_t)(r0 + 3) * (WW / 4)];

        unsigned pk = 0;
        int rmin_t = 255, rmax_t = 0;
        unsigned cm4 = 0;

#define PROC(v, r)                                                             \
        {                                                                      \
            float mn = fminf(fminf(v.x, v.y), fminf(v.z, v.w));                \
            float mx = fmaxf(fmaxf(v.x, v.y), fmaxf(v.z, v.w));                \
            if (mx > -1.f) {                                                   \
                if (mn > 1.f) {                                                \
                    pk += 0x00040004u;                                         \
                    rmin_t = min(rmin_t, r);                                   \
                    rmax_t = r;                                                \
                    cm4 |= 0xFu;                                               \
                } else {                                                       \
                    int h = (v.x > 1.f) + (v.y > 1.f) + (v.z > 1.f) +          \
                            (v.w > 1.f);                                       \
                    int l = (v.x > -1.f) + (v.y > -1.f) + (v.z > -1.f) +       \
                            (v.w > -1.f);                                      \
                    pk += ((unsigned)h << 16) + (unsigned)l;                   \
                    unsigned m = (v.x > 0.f) | ((v.y > 0.f) << 1) |            \
                                 ((v.z > 0.f) << 2) | ((v.w > 0.f) << 3);      \
                    if (m) {                                                   \
                        rmin_t = min(rmin_t, r);                               \
                        rmax_t = r;                                            \
                        cm4 |= m;                                              \
                    }                                                          \
                }                                                              \
            }                                                                  \
        }

        PROC(v0, r0 + 0)
        PROC(v1, r0 + 1)
        PROC(v2, r0 + 2)
        PROC(v3, r0 + 3)
#undef PROC

        unsigned p;
        if (cm4) {
            int cmin_t = col0 + (__ffs(cm4) - 1);
            int cmax_t = col0 + (31 - __clz(cm4));
            p = ((unsigned)rmin_t << 24) | ((unsigned)(255 - rmax_t) << 16) |
                ((unsigned)cmin_t << 8) | (unsigned)(255 - cmax_t);
        } else {
            p = 0xFFFFFFFFu;
        }

#pragma unroll
        for (int o = 16; o > 0; o >>= 1) {
            p  = __vminu4(p, __shfl_down_sync(0xffffffffu, p, o));
            pk += __shfl_down_sync(0xffffffffu, pk, o);
        }

        const int warp = tid >> 5;
        if ((tid & 31) == 0) { s_p[warp] = p; s_pk[warp] = pk; }
        __syncthreads();
        if (tid == 0) {
            unsigned P = s_p[0], K = s_pk[0];
#pragma unroll
            for (int w = 1; w < 8; w++) { P = __vminu4(P, s_p[w]); K += s_pk[w]; }
            const int gidx = q * NM + n;
            g_pp[gidx] = P;
            g_pk[gidx] = K;
        }
    }

    // ---- arrival (release) ----
    __threadfence();
    __syncthreads();
    if (tid == 0) {
        unsigned prev = atomicAdd(&g_arrive, 1u);
        s_last = (prev == NBLK - 1) ? 1 : 0;
    }
    __syncthreads();
    if (!s_last) return;

    // ================= NMS by the last-arriving block (256 thr) =============
    __threadfence();   // acquire: all g_pp/g_pk writes now visible
    if (tid == 0) { s_cnt = 0; s_kc = 0; }
    __syncthreads();

#pragma unroll
    for (int w = 0; w < 4; w++) {
        const int m = tid + w * 256;
        unsigned P = 0xFFFFFFFFu, K = 0;
#pragma unroll
        for (int q = 0; q < NQ; q++) {
            const int idx = q * NM + m;
            P = __vminu4(P, g_pp[idx]);
            K += g_pk[idx];
        }
        const int hi = (int)(K >> 16);
        const int lo = (int)(K & 0xFFFFu);

        float4 box;
        if (P == 0xFFFFFFFFu) {
            box = make_float4(0.f, 0.f, 0.f, 0.f);
        } else {
            box = make_float4((float)((P >> 8) & 0xFF),
                              (float)(P >> 24),
                              (float)(255 - (P & 0xFF)),
                              (float)(255 - ((P >> 16) & 0xFF)));
        }
        gx_bx[m] = box;

        const float ip   = iou[m];
        const float stab = (float)hi / fmaxf((float)lo, 1.0f);
        if ((ip > 0.88f) && (stab >= 0.95f)) {
            int pos = atomicAdd(&s_cnt, 1);
            gx_csc[pos] = ip;
            gx_cid[pos] = m;
        }
        g_gated[m] = 0.f;
        if (write_extra) {
            out_keep[m] = 0.f;
            reinterpret_cast<float4*>(out_boxes)[m] = box;
        }
    }
    __syncthreads();   // orders global scratch within block
    const int V = s_cnt;

    if (V > 0) {
        // ---- O(V^2) rank (deterministic, desc score / asc idx) ----
        for (int c = tid; c < V; c += 256) {
            const float ms = gx_csc[c];
            const int   mi = gx_cid[c];
            int rank = 0;
            for (int j = 0; j < V; j++) {
                float sj = gx_csc[j];
                rank += (sj > ms) | ((sj == ms) & (gx_cid[j] < mi));
            }
            gx_sc[rank] = ms;
            gx_ord[rank] = mi;
        }
        __syncthreads();

        for (int c = tid; c < V; c += 256) {
            float4 b = gx_bx[gx_ord[c]];
            gx_area[c] = fmaxf(b.z - b.x, 0.f) * fmaxf(b.w - b.y, 0.f);
        }
        __syncthreads();

        if (V <= 256) {
            if (tid < V) {
                const float4 bi = gx_bx[gx_ord[tid]];
                const float  ai = gx_area[tid];
                unsigned w[8] = {0, 0, 0, 0, 0, 0, 0, 0};
                for (int j = tid + 1; j < V; j++) {
                    const float4 bj = gx_bx[gx_ord[j]];
                    float x0 = fmaxf(bi.x, bj.x), y0 = fmaxf(bi.y, bj.y);
                    float x1 = fminf(bi.z, bj.z), y1 = fminf(bi.w, bj.w);
                    float inter = fmaxf(x1 - x0, 0.f) * fmaxf(y1 - y0, 0.f);
                    float v = inter / fmaxf(ai + gx_area[j] - inter, 1e-6f);
                    if (v > 0.7f) w[j >> 5] |= 1u << (j & 31);
                }
#pragma unroll
                for (int k = 0; k < 8; k++) gx_sup[tid * 8 + k] = w[k];
            }
            __syncthreads();

            if (tid == 0) {
                unsigned live[8];
#pragma unroll
                for (int k = 0; k < 8; k++) {
                    int rem = V - k * 32;
                    live[k] = (rem >= 32) ? 0xffffffffu
                                          : (rem > 0 ? ((1u << rem) - 1u) : 0u);
                }
                for (int i = 0; i < V; i++) {
                    if ((live[i >> 5] >> (i & 31)) & 1u) {
#pragma unroll
                        for (int k = 0; k < 8; k++) live[k] &= ~gx_sup[i * 8 + k];
                    }
                }
#pragma unroll
                for (int k = 0; k < 8; k++) s_live[k] = live[k];
            }
            __syncthreads();

            // kept overrides + kept list (disjoint regions -> order-free)
            if (tid < V && ((s_live[tid >> 5] >> (tid & 31)) & 1u)) {
                const int oi = gx_ord[tid];
                g_gated[oi] = gx_sc[tid];
                if (write_extra) out_keep[oi] = 1.f;
                const int slot = atomicAdd(&s_kc, 1);
                g_klist[slot] = oi;
            }
        } else {
            // ---- fallback: iterative greedy, strided (rare) ----
            // reuse gx_sup[c] slot 0 as keep flag storage via gx_cid trick:
            // simpler: use gx_csc as keep flags (no longer needed)
            for (int c = tid; c < V; c += 256) gx_csc[c] = 1.0f;
            __syncthreads();
            for (int i = 0; i < V; i++) {
                if (gx_csc[i] != 0.0f) {
                    const float4 pb = gx_bx[gx_ord[i]];
                    const float  pa = gx_area[i];
                    for (int c = tid; c < V; c += 256) {
                        if (c > i && gx_csc[c] != 0.0f) {
                            const float4 mb = gx_bx[gx_ord[c]];
                            float x0 = fmaxf(pb.x, mb.x), y0 = fmaxf(pb.y, mb.y);
                            float x1 = fminf(pb.z, mb.z), y1 = fminf(pb.w, mb.w);
                            float inter = fmaxf(x1 - x0, 0.f) * fmaxf(y1 - y0, 0.f);
                            float v = inter / fmaxf(pa + gx_area[c] - inter, 1e-6f);
                            if (v > 0.7f) gx_csc[c] = 0.0f;
                        }
                    }
                }
                __syncthreads();
            }
            for (int c = tid; c < V; c += 256) {
                if (gx_csc[c] != 0.0f) {
                    const int oi = gx_ord[c];
                    g_gated[oi] = gx_sc[c];
                    if (write_extra) out_keep[oi] = 1.f;
                    const int slot = atomicAdd(&s_kc, 1);
                    g_klist[slot] = oi;
                }
            }
        }
    }
    __syncthreads();
    if (tid == 0) { g_kcnt = s_kc; g_arrive = 0; }
}

// ---------------------------------------------------------------------------
// Kernel B: kept-only pass via kept-list indirection. grid = (16, 256),
// 256 threads. Block (x, y) handles 4 KB-chunk x of kept masks y, y+256, ...
// Non-working blocks exit after a single load of g_kcnt.
// ---------------------------------------------------------------------------
__global__ void __launch_bounds__(256) out_kernel(const float* __restrict__ logits,
                                                  float* __restrict__ out) {
    const int kc = g_kcnt;
    const int tid = threadIdx.x;

    for (int s = blockIdx.y; s < kc; s += 256) {
        const int n = g_klist[s];
        const float g = g_gated[n];
        const size_t base = (size_t)n * HW + (size_t)blockIdx.x * 4096;
        const float4* __restrict__ in4 = reinterpret_cast<const float4*>(logits + base);
        float4* __restrict__ o4 = reinterpret_cast<float4*>(out + base);

#pragma unroll
        for (int k = 0; k < 4; k++) {
            float4 v = in4[k * 256 + tid];
            float4 r;
            r.x = g / (1.f + __expf(-v.x));
            r.y = g / (1.f + __expf(-v.y));
            r.z = g / (1.f + __expf(-v.z));
            r.w = g / (1.f + __expf(-v.w));
            o4[k * 256 + tid] = r;
        }
    }
}

// ---------------------------------------------------------------------------
extern "C" void kernel_launch(void* const* d_in, const int* in_sizes, int n_in,
                              void* d_out, int out_size) {
    const float* logits = (const float*)d_in[0];
    const float* iou    = (const float*)d_in[1];
    if (n_in >= 2 && in_sizes[0] == NM && in_sizes[1] == NM * HW) {
        logits = (const float*)d_in[1];
        iou    = (const float*)d_in[0];
    }

    float* out = (float*)d_out;
    const long long NHW = (long long)NM * HW;
    int write_extra = (out_size >= NHW + NM + NM * 4) ? 1 : 0;
    float* out_keep  = out + NHW;
    float* out_boxes = out + NHW + NM;

    stats_zero_nms_kernel<<<NBLK, 256>>>(logits, out, iou, out_keep, out_boxes, write_extra);
    out_kernel<<<dim3(16, 256), 256>>>(logits, out);
}